// round 4
// baseline (speedup 1.0000x reference)
#include <cuda_runtime.h>

// Problem constants (from reference): x[16,32,256,256], w[32,32,3,3], bias[32]
#define NN   16
#define CIN  32
#define COUT 32
#define HH   256
#define WW   256
#define TILE 16
#define IN_ROWS 18          // TILE + 2 halo
#define IN_PITCH 20         // padded pitch: 4*20=80 ≡ 16 (mod 32) -> conflict-free with sx span 16
#define IN_CH_STRIDE (IN_ROWS * IN_PITCH)   // 360 floats per channel
#define W_CH_STRIDE  (9 * COUT)             // 288 floats per cin in [cin][k][co] layout

#define SMEM_FLOATS (CIN * IN_CH_STRIDE + CIN * W_CH_STRIDE)   // 11520 + 9216 = 20736
#define SMEM_BYTES  (SMEM_FLOATS * 4)                          // 82944

__device__ __forceinline__ unsigned long long pack2(float a, float b) {
    unsigned long long r;
    asm("mov.b64 %0, {%1, %2};" : "=l"(r) : "f"(a), "f"(b));
    return r;
}

__device__ __forceinline__ void fma2(unsigned long long& d, unsigned long long a, unsigned long long b) {
    // d = a * b + d  (packed 2x fp32)
    asm("fma.rn.f32x2 %0, %1, %2, %0;" : "+l"(d) : "l"(a), "l"(b));
}

__device__ __forceinline__ float2 unpack2(unsigned long long v) {
    float2 r;
    asm("mov.b64 {%0, %1}, %2;" : "=f"(r.x), "=f"(r.y) : "l"(v));
    return r;
}

__global__ __launch_bounds__(256, 2)
void conv3x3_kernel(const float* __restrict__ x,
                    const float* __restrict__ w,
                    const float* __restrict__ bias,
                    float* __restrict__ out)
{
    extern __shared__ float smem[];
    float* in_s = smem;                               // [32][18][20]
    float* w_s  = smem + CIN * IN_CH_STRIDE;          // [cin][k][co] = [32][9][32]

    const int tid = threadIdx.x;
    const int n   = blockIdx.z;

    // ---- cooperative load: weights, transposed OIHW -> [cin][k][co] ----
    // global w layout: co*(CIN*9) + cin*9 + k
    #pragma unroll 4
    for (int idx = tid; idx < COUT * CIN * 9; idx += 256) {
        int co = idx / (CIN * 9);
        int r  = idx - co * (CIN * 9);
        int ci = r / 9;
        int k  = r - ci * 9;
        w_s[ci * W_CH_STRIDE + k * COUT + co] = w[idx];
    }

    // ---- cooperative load: input tile with halo, zero-padded at borders ----
    const int x0 = blockIdx.x * TILE - 1;
    const int y0 = blockIdx.y * TILE - 1;
    const float* xin = x + (size_t)n * CIN * HH * WW;

    #pragma unroll 4
    for (int idx = tid; idx < CIN * IN_ROWS * IN_ROWS; idx += 256) {
        int c  = idx / (IN_ROWS * IN_ROWS);
        int r  = idx - c * (IN_ROWS * IN_ROWS);
        int ry = r / IN_ROWS;
        int rx = r - ry * IN_ROWS;
        int gy = y0 + ry;
        int gx = x0 + rx;
        float v = 0.0f;
        if ((unsigned)gy < (unsigned)HH && (unsigned)gx < (unsigned)WW)
            v = xin[(c * HH + gy) * WW + gx];
        in_s[c * IN_CH_STRIDE + ry * IN_PITCH + rx] = v;
    }

    __syncthreads();

    // ---- thread mapping: 4 channel-groups x 64 pixel slots ----
    const int cg  = tid >> 6;          // 0..3  -> output channels cg*8 .. cg*8+7
    const int s   = tid & 63;
    const int sx  = s & 15;            // column in tile
    const int sy  = s >> 4;            // 0..3  -> rows sy*4 .. sy*4+3
    const int row0 = sy * 4;

    const float* ip    = in_s + row0 * IN_PITCH + sx;
    const float* wbase = w_s + cg * 8;

    // accumulators: 4 channel-pairs x 4 pixels, initialized with bias
    unsigned long long acc[4][4];
    #pragma unroll
    for (int j = 0; j < 4; j++) {
        unsigned long long bb = pack2(bias[cg * 8 + 2 * j], bias[cg * 8 + 2 * j + 1]);
        #pragma unroll
        for (int p = 0; p < 4; p++) acc[j][p] = bb;
    }

    // ---- main loop over input channels ----
    #pragma unroll 1
    for (int ci = 0; ci < CIN; ci++) {
        const float* ipc = ip + ci * IN_CH_STRIDE;
        const float* wpc = wbase + ci * W_CH_STRIDE;

        // preload the 6x3 input window this thread needs (rows row0..row0+5, cols sx..sx+2)
        unsigned long long vv[6][3];
        #pragma unroll
        for (int r = 0; r < 6; r++) {
            #pragma unroll
            for (int c = 0; c < 3; c++) {
                float t = ipc[r * IN_PITCH + c];
                vv[r][c] = pack2(t, t);
            }
        }

        #pragma unroll
        for (int ky = 0; ky < 3; ky++) {
            #pragma unroll
            for (int kx = 0; kx < 3; kx++) {
                const float* wk = wpc + (ky * 3 + kx) * COUT;
                #pragma unroll
                for (int j = 0; j < 4; j++) {
                    // 64-bit broadcast load of a channel-pair of weights
                    unsigned long long wp =
                        *reinterpret_cast<const unsigned long long*>(wk + 2 * j);
                    #pragma unroll
                    for (int p = 0; p < 4; p++)
                        fma2(acc[j][p], wp, vv[p + ky][kx]);
                }
            }
        }
    }

    // ---- epilogue: write 8 channels x 4 pixels ----
    float* obase = out + (size_t)n * COUT * HH * WW;
    const int ox  = blockIdx.x * TILE + sx;
    const int oy0 = blockIdx.y * TILE + row0;

    #pragma unroll
    for (int j = 0; j < 4; j++) {
        const int co = cg * 8 + 2 * j;
        float* o0 = obase + (size_t)co * HH * WW;
        #pragma unroll
        for (int p = 0; p < 4; p++) {
            float2 r = unpack2(acc[j][p]);
            o0[(oy0 + p) * WW + ox]           = r.x;
            o0[HH * WW + (oy0 + p) * WW + ox] = r.y;
        }
    }
}

extern "C" void kernel_launch(void* const* d_in, const int* in_sizes, int n_in,
                              void* d_out, int out_size)
{
    const float* x    = (const float*)d_in[0];
    const float* w    = (const float*)d_in[1];
    const float* bias = (const float*)d_in[2];
    float* out        = (float*)d_out;

    // 82944 B dynamic smem > 48KB default: raise the cap (host-side attribute,
    // idempotent, not a stream op -> graph-capture safe)
    (void)cudaFuncSetAttribute(conv3x3_kernel,
                               cudaFuncAttributeMaxDynamicSharedMemorySize, SMEM_BYTES);

    dim3 grid(WW / TILE, HH / TILE, NN);   // 16 x 16 x 16
    conv3x3_kernel<<<grid, 256, SMEM_BYTES>>>(x, w, bias, out);
}

// round 7
// speedup vs baseline: 1.1209x; 1.1209x over previous
#include <cuda_runtime.h>

// x[16,32,256,256], w[32,32,3,3], bias[32], out[16,32,256,256]
#define NN   16
#define CIN  32
#define COUT 32
#define HH   256
#define WW   256
#define TW   16            // tile width
#define TH   32            // tile height
#define IN_COLS 18         // TW + 2 halo
#define IN_ROWS 34         // TH + 2 halo
#define IN_PITCH 18        // 8-row step: 8*18=144 ≡ 16 (mod 32) -> conflict-free half-warps
#define IN_CH_STRIDE (IN_ROWS * IN_PITCH)   // 612 floats
#define W_CH_STRIDE  (9 * COUT)             // 288 floats, layout [cin][k][co]

#define SMEM_FLOATS (CIN * IN_CH_STRIDE + CIN * W_CH_STRIDE)  // 19584 + 9216 = 28800
#define SMEM_BYTES  (SMEM_FLOATS * 4)                         // 115200

__device__ __forceinline__ unsigned long long pack2(float a, float b) {
    unsigned long long r;
    asm("mov.b64 %0, {%1, %2};" : "=l"(r) : "f"(a), "f"(b));
    return r;
}

__device__ __forceinline__ void fma2(unsigned long long& d, unsigned long long a, unsigned long long b) {
    asm("fma.rn.f32x2 %0, %1, %2, %0;" : "+l"(d) : "l"(a), "l"(b));
}

__device__ __forceinline__ float2 unpack2(unsigned long long v) {
    float2 r;
    asm("mov.b64 {%0, %1}, %2;" : "=f"(r.x), "=f"(r.y) : "l"(v));
    return r;
}

__global__ __launch_bounds__(256, 1)
void conv3x3_kernel(const float* __restrict__ x,
                    const float* __restrict__ w,
                    const float* __restrict__ bias,
                    float* __restrict__ out)
{
    extern __shared__ float smem[];
    float* in_s = smem;                         // [32][34][18]
    float* w_s  = smem + CIN * IN_CH_STRIDE;    // [cin][9][32]

    const int tid = threadIdx.x;
    const int n   = blockIdx.z;

    // ---- weights: OIHW -> [cin][k][co] ----
    #pragma unroll 4
    for (int idx = tid; idx < COUT * CIN * 9; idx += 256) {
        int co = idx / (CIN * 9);
        int r  = idx - co * (CIN * 9);
        int ci = r / 9;
        int k  = r - ci * 9;
        w_s[ci * W_CH_STRIDE + k * COUT + co] = w[idx];
    }

    // ---- input tile + halo, zero-padded ----
    const int x0 = blockIdx.x * TW - 1;
    const int y0 = blockIdx.y * TH - 1;
    const float* xin = x + (size_t)n * CIN * HH * WW;

    #pragma unroll 4
    for (int idx = tid; idx < CIN * IN_ROWS * IN_COLS; idx += 256) {
        int c  = idx / (IN_ROWS * IN_COLS);
        int r  = idx - c * (IN_ROWS * IN_COLS);
        int ry = r / IN_COLS;
        int rx = r - ry * IN_COLS;
        int gy = y0 + ry;
        int gx = x0 + rx;
        float v = 0.0f;
        if ((unsigned)gy < (unsigned)HH && (unsigned)gx < (unsigned)WW)
            v = xin[(c * HH + gy) * WW + gx];
        in_s[c * IN_CH_STRIDE + ry * IN_PITCH + rx] = v;
    }

    __syncthreads();

    // ---- mapping: 4 channel-groups x 64 pixel slots (16 cols x 4 row-bands of 8) ----
    const int cg   = tid >> 6;        // co group: channels 8*cg .. 8*cg+7
    const int s    = tid & 63;
    const int sx   = s & 15;
    const int sy   = s >> 4;          // 0..3
    const int row0 = sy * 8;

    const float* ip    = in_s + row0 * IN_PITCH + sx;
    const float* wbase = w_s + cg * 8;

    // 4 channel-pairs x 8 pixels
    unsigned long long acc[4][8];
    #pragma unroll
    for (int j = 0; j < 4; j++) {
        unsigned long long bb = pack2(bias[cg * 8 + 2 * j], bias[cg * 8 + 2 * j + 1]);
        #pragma unroll
        for (int p = 0; p < 8; p++) acc[j][p] = bb;
    }

    #pragma unroll 1
    for (int ci = 0; ci < CIN; ci++) {
        const float* ipc = ip + ci * IN_CH_STRIDE;
        const float* wpc = wbase + ci * W_CH_STRIDE;

        // preload 10x3 input window (rows row0..row0+9, cols sx..sx+2)
        unsigned long long vv[10][3];
        #pragma unroll
        for (int r = 0; r < 10; r++) {
            #pragma unroll
            for (int c = 0; c < 3; c++) {
                float t = ipc[r * IN_PITCH + c];
                vv[r][c] = pack2(t, t);
            }
        }

        #pragma unroll
        for (int ky = 0; ky < 3; ky++) {
            #pragma unroll
            for (int kx = 0; kx < 3; kx++) {
                const float* wk = wpc + (ky * 3 + kx) * COUT;
                // two 128-bit broadcast loads: 4 channel-pairs of weights
                float4 wA = *reinterpret_cast<const float4*>(wk);
                float4 wB = *reinterpret_cast<const float4*>(wk + 4);
                unsigned long long wp[4];
                wp[0] = pack2(wA.x, wA.y);
                wp[1] = pack2(wA.z, wA.w);
                wp[2] = pack2(wB.x, wB.y);
                wp[3] = pack2(wB.z, wB.w);
                #pragma unroll
                for (int j = 0; j < 4; j++) {
                    #pragma unroll
                    for (int p = 0; p < 8; p++)
                        fma2(acc[j][p], wp[j], vv[p + ky][kx]);
                }
            }
        }
    }

    // ---- epilogue: 8 channels x 8 pixels ----
    float* obase = out + (size_t)n * COUT * HH * WW;
    const int ox  = blockIdx.x * TW + sx;
    const int oy0 = blockIdx.y * TH + row0;

    #pragma unroll
    for (int j = 0; j < 4; j++) {
        const int co = cg * 8 + 2 * j;
        float* o0 = obase + (size_t)co * HH * WW;
        #pragma unroll
        for (int p = 0; p < 8; p++) {
            float2 r = unpack2(acc[j][p]);
            o0[(oy0 + p) * WW + ox]           = r.x;
            o0[HH * WW + (oy0 + p) * WW + ox] = r.y;
        }
    }
}

extern "C" void kernel_launch(void* const* d_in, const int* in_sizes, int n_in,
                              void* d_out, int out_size)
{
    const float* x    = (const float*)d_in[0];
    const float* w    = (const float*)d_in[1];
    const float* bias = (const float*)d_in[2];
    float* out        = (float*)d_out;

    (void)cudaFuncSetAttribute(conv3x3_kernel,
                               cudaFuncAttributeMaxDynamicSharedMemorySize, SMEM_BYTES);

    dim3 grid(WW / TW, HH / TH, NN);   // 16 x 8 x 16 = 2048
    conv3x3_kernel<<<grid, 256, SMEM_BYTES>>>(x, w, bias, out);
}